// round 11
// baseline (speedup 1.0000x reference)
#include <cuda_runtime.h>
#include <cuda_fp16.h>
#include <cstdint>

#define NNODE 8192
#define NEDGE 253952

__device__ __half d_PQh[6 * NNODE * 256];      // [e*2+half][node][256] fp16
__device__ float  d_G  [3 * NEDGE];
__device__ float  d_AGGe[3 * NNODE * 256];     // per-expert partial agg
__device__ __half d_Wh[3 * 256 * 256];         // [e][n][k] fp16

__device__ __forceinline__ float lrelu(float v) { return fmaxf(v, 0.01f * v); }

__device__ __forceinline__ uint32_t smem_u32(const void* p) {
    uint32_t a;
    asm("{ .reg .u64 t; cvta.to.shared.u64 t, %1; cvt.u32.u64 %0, t; }" : "=r"(a) : "l"(p));
    return a;
}
__device__ __forceinline__ unsigned long long dup2(float w) {
    unsigned long long r; unsigned int u = __float_as_uint(w);
    asm("mov.b64 %0, {%1, %1};" : "=l"(r) : "r"(u));
    return r;
}
__device__ __forceinline__ void ffma2(unsigned long long& d,
                                      unsigned long long a, unsigned long long b) {
    asm("fma.rn.f32x2 %0, %1, %2, %0;" : "+l"(d) : "l"(a), "l"(b));
}
__device__ __forceinline__ float lo32(unsigned long long v) {
    return __uint_as_float((unsigned int)(v & 0xffffffffull));
}
__device__ __forceinline__ float hi32(unsigned long long v) {
    return __uint_as_float((unsigned int)(v >> 32));
}

#define CP_ASYNC16(dst, src) \
    asm volatile("cp.async.cg.shared.global [%0], [%1], 16;" :: "r"(dst), "l"(src) : "memory")
#define CP_COMMIT() asm volatile("cp.async.commit_group;" ::: "memory")
#define CP_WAIT(n)  asm volatile("cp.async.wait_group %0;" :: "n"(n) : "memory")

#define LDSM_X4(r, a) \
    asm volatile("ldmatrix.sync.aligned.m8n8.x4.shared.b16 {%0,%1,%2,%3}, [%4];" \
        : "=r"((r)[0]), "=r"((r)[1]), "=r"((r)[2]), "=r"((r)[3]) : "r"(a))
#define MMA16816(d, a, b) \
    asm volatile("mma.sync.aligned.m16n8k16.row.col.f32.f16.f16.f32 " \
        "{%0,%1,%2,%3}, {%4,%5,%6,%7}, {%8,%9}, {%0,%1,%2,%3};" \
        : "+f"((d)[0]), "+f"((d)[1]), "+f"((d)[2]), "+f"((d)[3]) \
        : "r"((a)[0]), "r"((a)[1]), "r"((a)[2]), "r"((a)[3]), "r"((b)[0]), "r"((b)[1]))

// ------------------------- k1g: edge gates ---------------------------------
__global__ void k1g(const float* __restrict__ state, const float4* __restrict__ rt4) {
    int idx = blockIdx.x * blockDim.x + threadIdx.x;
    if (idx >= NEDGE) return;
    int bt = idx / 992, r = idx - bt * 992;
    int b = bt >> 6, t = bt & 63;
    int rec = r / 31, j = r - rec * 31;
    int send = j + (j >= rec);
    const float4 st = *(const float4*)&state[(((b * 32 + send) * 64) + t) * 4];
    const float4* rt = rt4 + (b * 992 + r) * 4;
    float4 r0 = rt[0], r1 = rt[1], r2 = rt[2], r3 = rt[3];
    d_G[0 * NEDGE + idx] = st.x * r0.y + st.y * r1.y + st.z * r2.y + st.w * r3.y;
    d_G[1 * NEDGE + idx] = st.x * r0.z + st.y * r1.z + st.z * r2.z + st.w * r3.z;
    d_G[2 * NEDGE + idx] = st.x * r0.w + st.y * r1.w + st.z * r2.w + st.w * r3.w;
}

// --------- k2: P/Q node GEMMs -> fp16 (fused transpose, FFMA2) -------------
// 128 blocks x 256 threads; 64 node rows per block. xs transposed [k][m] s66.
__global__ __launch_bounds__(256) void k2(const float4* __restrict__ in4,
                                          const float* __restrict__ w1,
                                          const float* __restrict__ b1) {
    __shared__ float xs[64 * 66];
    int row0 = blockIdx.x * 64, tid = threadIdx.x;
    for (int i = tid; i < 64 * 16; i += 256) {
        int m = i >> 4, q = i & 15;
        int n = row0 + m, b = n >> 11, t = (n >> 5) & 63, a = n & 31;
        float4 v = in4[(((b * 32 + a) * 64) + t) * 16 + q];
        xs[(4 * q + 0) * 66 + m] = v.x;
        xs[(4 * q + 1) * 66 + m] = v.y;
        xs[(4 * q + 2) * 66 + m] = v.z;
        xs[(4 * q + 3) * 66 + m] = v.w;
    }
    __syncthreads();
    for (int chunk = 0; chunk < 6; ++chunk) {
        int e = chunk >> 1, half = chunk & 1;
        const float* W = w1 + ((size_t)((e + 1) * 128 + half * 64)) * 256;
        unsigned long long acc2[32];
#pragma unroll
        for (int mp = 0; mp < 32; ++mp) acc2[mp] = 0ull;
#pragma unroll 2
        for (int k = 0; k < 64; ++k) {
            unsigned long long wd = dup2(W[k * 256 + tid]);
            const unsigned long long* xp = (const unsigned long long*)(xs + k * 66);
#pragma unroll
            for (int mp = 0; mp < 32; ++mp) ffma2(acc2[mp], xp[mp], wd);
        }
        float bias = (half == 0) ? b1[(e + 1) * 256 + tid] : 0.f;
        __half* dst = d_PQh + ((size_t)chunk * NNODE + row0) * 256 + tid;
#pragma unroll
        for (int mp = 0; mp < 32; ++mp) {
            dst[(2 * mp) * 256]     = __float2half(lo32(acc2[mp]) + bias);
            dst[(2 * mp + 1) * 256] = __float2half(hi32(acc2[mp]) + bias);
        }
    }
}

// --------------- k2w: W2 transpose -> fp16 [e][n][k] -----------------------
__global__ void k2w(const float* __restrict__ w2) {
    __shared__ float tile[32][33];
    int e = blockIdx.z, kt = blockIdx.x * 32, nt = blockIdx.y * 32;
    int tx = threadIdx.x, ty = threadIdx.y;          // 32 x 8
#pragma unroll
    for (int r = 0; r < 4; ++r)
        tile[ty + r * 8][tx] = w2[((size_t)(e + 1) * 256 + kt + ty + r * 8) * 256 + nt + tx];
    __syncthreads();
#pragma unroll
    for (int r = 0; r < 4; ++r) {
        int n = nt + ty + r * 8;
        d_Wh[((size_t)e * 256 + n) * 256 + kt + tx] = __float2half(tile[tx][ty + r * 8]);
    }
}

// ------------- k3g: B-resident fp16 HMMA edge GEMM (2 syncs/tile) ----------
// Grid = 3 experts x 48 blocks; 43/42 quad-tiles per block. Full-K A built
// per tile directly from L2-resident fp16 P/Q; barrier-free MMA over 4 kc.
#define SB_B    0            // 256 x 528 = 135168
#define SB_A    135168       // 128 x 528 = 67584
#define SB_G    202752       // 512
#define SB_B2   203264       // 1024
#define K3G_SMEM 204288

__global__ __launch_bounds__(512, 1) void k3g(const float* __restrict__ b2) {
    extern __shared__ char smem[];
    uint32_t sb = smem_u32(smem);
    int tid = threadIdx.x, lane = tid & 31, wid = tid >> 5;
    int mwarp = wid >> 2, nwarp = wid & 3;
    int e = blockIdx.x / 48, jb = blockIdx.x % 48;
    int t0     = (jb < 32) ? jb * 43 : 32 * 43 + (jb - 32) * 42;
    int ntiles = (jb < 32) ? 43 : 42;

    float* g_s = (float*)(smem + SB_G);
    float* b2s = (float*)(smem + SB_B2);
    const __half* Pg = d_PQh + (size_t)(e * 2) * NNODE * 256;
    const __half* Qg = d_PQh + (size_t)(e * 2 + 1) * NNODE * 256;

    auto cvt = [](uint32_t pa, uint32_t qa) -> uint32_t {
        __half2 h = __hadd2(*(__half2*)&pa, *(__half2*)&qa);
        __half2 s = __hmul2(h, __float2half2_rn(0.01f));
        __half2 r = __hmax2(h, s);
        return *(uint32_t*)&r;
    };

    // ---- prologue: b2 + full B resident ----
    if (tid < 256) b2s[tid] = b2[(e + 1) * 256 + tid];
    {
        const __half* Wsrc = d_Wh + (size_t)e * 65536;
        for (int i = tid; i < 8192; i += 512) {
            int n = i >> 5, c = i & 31;
            CP_ASYNC16(sb + SB_B + (uint32_t)(n * 528 + c * 16),
                       (const char*)(Wsrc + n * 256 + c * 8));
        }
        CP_COMMIT();
    }
    CP_WAIT(0);
    __syncthreads();

    for (int ti = 0; ti < ntiles; ++ti) {
        int t = t0 + ti;
        int bt = t >> 3, a0 = (t & 7) * 4;

        // ---- build full-K A directly from L2 fp16 P/Q ----
        {
            int m = tid >> 2, sub = tid & 3;
            int mq = m >> 5, jj = m & 31;
            int rec = a0 + mq;
            int send = (jj < 31) ? (jj + (jj >= rec)) : 0;   // dummy rows gated
            const uint4* P4 = (const uint4*)(Pg + ((size_t)(bt * 32 + send)) * 256 + sub * 64);
            const uint4* Q4 = (const uint4*)(Qg + ((size_t)(bt * 32 + rec)) * 256 + sub * 64);
            uint4* dst = (uint4*)(smem + SB_A + m * 528 + sub * 128);
#pragma unroll
            for (int q = 0; q < 8; ++q) {
                uint4 p = P4[q], qq = Q4[q];
                uint4 o;
                o.x = cvt(p.x, qq.x); o.y = cvt(p.y, qq.y);
                o.z = cvt(p.z, qq.z); o.w = cvt(p.w, qq.w);
                dst[q] = o;
            }
        }
        if (tid < 128) {
            int grp = tid >> 5, jj = tid & 31;
            g_s[tid] = (jj < 31)
                ? d_G[(size_t)e * NEDGE + bt * 992 + (a0 + grp) * 31 + jj] : 0.f;
        }
        __syncthreads();

        float acc[2][8][4];
#pragma unroll
        for (int ms = 0; ms < 2; ++ms)
#pragma unroll
            for (int ns = 0; ns < 8; ++ns)
#pragma unroll
                for (int c = 0; c < 4; ++c) acc[ms][ns][c] = 0.f;

        uint32_t a_l = sb + SB_A
                     + (uint32_t)(mwarp * 32 + (lane & 7) + ((lane >> 3) & 1) * 8) * 528u
                     + ((lane >> 4) & 1) * 16u;
        uint32_t b_l = sb + SB_B
                     + (uint32_t)(nwarp * 64 + (lane & 7) + ((lane >> 4) & 1) * 8) * 528u
                     + ((lane >> 3) & 1) * 16u;
#pragma unroll
        for (int kc = 0; kc < 4; ++kc) {
#pragma unroll
            for (int ks = 0; ks < 4; ++ks) {
                uint32_t koff = (uint32_t)(kc * 128 + ks * 32);
                uint32_t af0[4], af1[4];
                LDSM_X4(af0, a_l + koff);
                LDSM_X4(af1, a_l + 16 * 528 + koff);
#pragma unroll
                for (int p = 0; p < 4; ++p) {
                    uint32_t bf[4];
                    LDSM_X4(bf, b_l + p * 8448 + koff);
                    MMA16816(acc[0][2 * p],     af0, bf);
                    MMA16816(acc[0][2 * p + 1], af0, bf + 2);
                    MMA16816(acc[1][2 * p],     af1, bf);
                    MMA16816(acc[1][2 * p + 1], af1, bf + 2);
                }
            }
        }

        // ---- epilogue: bias + lrelu + gate, reduce 32 rows/warp ----
        {
            float g00 = g_s[mwarp * 32 + (lane >> 2)];
            float g01 = g_s[mwarp * 32 + (lane >> 2) + 8];
            float g10 = g_s[mwarp * 32 + 16 + (lane >> 2)];
            float g11 = g_s[mwarp * 32 + 24 + (lane >> 2)];
            int node = bt * 32 + a0 + mwarp;
#pragma unroll
            for (int nst = 0; nst < 8; ++nst) {
                int c0 = nwarp * 64 + nst * 8 + (lane & 3) * 2;
                float b0v = b2s[c0], b1v = b2s[c0 + 1];
                float s0 = lrelu(acc[0][nst][0] + b0v) * g00 + lrelu(acc[0][nst][2] + b0v) * g01
                         + lrelu(acc[1][nst][0] + b0v) * g10 + lrelu(acc[1][nst][2] + b0v) * g11;
                float s1 = lrelu(acc[0][nst][1] + b1v) * g00 + lrelu(acc[0][nst][3] + b1v) * g01
                         + lrelu(acc[1][nst][1] + b1v) * g10 + lrelu(acc[1][nst][3] + b1v) * g11;
                s0 += __shfl_xor_sync(~0u, s0, 4);  s1 += __shfl_xor_sync(~0u, s1, 4);
                s0 += __shfl_xor_sync(~0u, s0, 8);  s1 += __shfl_xor_sync(~0u, s1, 8);
                s0 += __shfl_xor_sync(~0u, s0, 16); s1 += __shfl_xor_sync(~0u, s1, 16);
                if (lane < 4) {
                    float* dst = d_AGGe + ((size_t)e * NNODE + node) * 256 + c0;
                    dst[0] = s0; dst[1] = s1;
                }
            }
        }
        __syncthreads();   // A + g_s reuse next tile
    }
}

// ---- k5: output MLP + residual (64-row blocks, FFMA2, transposed smem) ----
#define K5_SMEM ((320 * 66 + 256 * 66) * 4)    // aug + hbuf = 152064

__global__ __launch_bounds__(256) void k5(const float4* __restrict__ in4,
                                          const float* __restrict__ fw1,
                                          const float* __restrict__ fb1,
                                          const float* __restrict__ fw2,
                                          const float* __restrict__ fb2,
                                          const float* __restrict__ fw3,
                                          const float* __restrict__ fb3,
                                          float* __restrict__ out) {
    extern __shared__ float sm5[];
    float* aug  = sm5;               // [320][66] transposed [k][m]
    float* hbuf = sm5 + 320 * 66;    // [256][66]
    int row0 = blockIdx.x * 64, tid = threadIdx.x;

    // stage x (transpose from inputs) into aug rows 0..63
    for (int i = tid; i < 64 * 16; i += 256) {
        int m = i >> 4, q = i & 15;
        int n = row0 + m, b = n >> 11, t = (n >> 5) & 63, a = n & 31;
        float4 v = in4[(((b * 32 + a) * 64) + t) * 16 + q];
        aug[(4 * q + 0) * 66 + m] = v.x;
        aug[(4 * q + 1) * 66 + m] = v.y;
        aug[(4 * q + 2) * 66 + m] = v.z;
        aug[(4 * q + 3) * 66 + m] = v.w;
    }
    // stage agg (sum of 3 experts, transposed) into aug rows 64..319
    for (int i = tid; i < 64 * 64; i += 256) {
        int m = i >> 6, jq = i & 63;
        size_t base = ((size_t)(row0 + m)) * 256 + jq * 4;
        float4 v0 = *(const float4*)(d_AGGe + base);
        float4 v1 = *(const float4*)(d_AGGe + (size_t)NNODE * 256 + base);
        float4 v2 = *(const float4*)(d_AGGe + (size_t)2 * NNODE * 256 + base);
        aug[(64 + 4 * jq + 0) * 66 + m] = v0.x + v1.x + v2.x;
        aug[(64 + 4 * jq + 1) * 66 + m] = v0.y + v1.y + v2.y;
        aug[(64 + 4 * jq + 2) * 66 + m] = v0.z + v1.z + v2.z;
        aug[(64 + 4 * jq + 3) * 66 + m] = v0.w + v1.w + v2.w;
    }
    __syncthreads();

    // layer 1: 320 -> 256 (thread = out col), FFMA2 over m-pairs
    {
        unsigned long long acc2[32];
#pragma unroll
        for (int mp = 0; mp < 32; ++mp) acc2[mp] = 0ull;
#pragma unroll 2
        for (int k = 0; k < 320; ++k) {
            unsigned long long wd = dup2(fw1[k * 256 + tid]);
            const unsigned long long* xp = (const unsigned long long*)(aug + k * 66);
#pragma unroll
            for (int mp = 0; mp < 32; ++mp) ffma2(acc2[mp], xp[mp], wd);
        }
        float b = fb1[tid];
#pragma unroll
        for (int mp = 0; mp < 32; ++mp) {
            float2 o;
            o.x = lrelu(lo32(acc2[mp]) + b);
            o.y = lrelu(hi32(acc2[mp]) + b);
            *(float2*)&hbuf[tid * 66 + 2 * mp] = o;
        }
    }
    __syncthreads();

    // layer 2: 256 -> 256 (output into aug rows 0..255, transposed)
    {
        unsigned long long acc2[32];
#pragma unroll
        for (int mp = 0; mp < 32; ++mp) acc2[mp] = 0ull;
#pragma unroll 2
        for (int k = 0; k < 256; ++k) {
            unsigned long long wd = dup2(fw2[k * 256 + tid]);
            const unsigned long long* xp = (const unsigned long long*)(hbuf + k * 66);
#pragma unroll
            for (int mp = 0; mp < 32; ++mp) ffma2(acc2[mp], xp[mp], wd);
        }
        float b = fb2[tid];
        __syncthreads();   // hbuf reads done before aug rows 0..255 overwritten? aug != hbuf; sync for aug readers below
#pragma unroll
        for (int mp = 0; mp < 32; ++mp) {
            float2 o;
            o.x = lrelu(lo32(acc2[mp]) + b);
            o.y = lrelu(hi32(acc2[mp]) + b);
            *(float2*)&aug[tid * 66 + 2 * mp] = o;
        }
    }
    __syncthreads();

    // layer 3: 256 -> 64, residual from inputs, write out (skip t = 63)
    {
        int c = tid & 63, sub = tid >> 6;       // 4 groups x 16 rows (8 pairs)
        unsigned long long acc2[8];
#pragma unroll
        for (int mp = 0; mp < 8; ++mp) acc2[mp] = 0ull;
#pragma unroll 2
        for (int k = 0; k < 256; ++k) {
            unsigned long long wd = dup2(fw3[k * 64 + c]);
            const unsigned long long* xp =
                (const unsigned long long*)(aug + k * 66 + sub * 16);
#pragma unroll
            for (int mp = 0; mp < 8; ++mp) ffma2(acc2[mp], xp[mp], wd);
        }
        float b = fb3[c];
#pragma unroll
        for (int mp = 0; mp < 8; ++mp) {
            float v0 = lo32(acc2[mp]) + b, v1 = hi32(acc2[mp]) + b;
#pragma unroll
            for (int h = 0; h < 2; ++h) {
                int n = row0 + sub * 16 + 2 * mp + h;
                int bb = n >> 11, t = (n >> 5) & 63, a = n & 31;
                if (t < 63) {
                    float x = ((const float*)in4)[(((bb * 32 + a) * 64) + t) * 64 + c];
                    out[(((bb * 32 + a) * 63) + t) * 64 + c] = x + (h ? v1 : v0);
                }
            }
        }
    }
}

// ---------------------------------------------------------------------------
extern "C" void kernel_launch(void* const* d_in, const int* in_sizes, int n_in,
                              void* d_out, int out_size) {
    (void)in_sizes; (void)n_in; (void)out_size;
    const float* inputs    = (const float*)d_in[0];
    const float* state     = (const float*)d_in[1];
    const float* rel_type  = (const float*)d_in[2];
    const float* msg_fc1_w = (const float*)d_in[5];
    const float* msg_fc1_b = (const float*)d_in[6];
    const float* msg_fc2_w = (const float*)d_in[7];
    const float* msg_fc2_b = (const float*)d_in[8];
    const float* out_fc1_w = (const float*)d_in[9];
    const float* out_fc1_b = (const float*)d_in[10];
    const float* out_fc2_w = (const float*)d_in[11];
    const float* out_fc2_b = (const float*)d_in[12];
    const float* out_fc3_w = (const float*)d_in[13];
    const float* out_fc3_b = (const float*)d_in[14];
    float* out = (float*)d_out;

    k1g<<<(NEDGE + 255) / 256, 256>>>(state, (const float4*)rel_type);
    k2<<<NNODE / 64, 256>>>((const float4*)inputs, msg_fc1_w, msg_fc1_b);
    k2w<<<dim3(8, 8, 3), dim3(32, 8)>>>(msg_fc2_w);

    cudaFuncSetAttribute(k3g, cudaFuncAttributeMaxDynamicSharedMemorySize, K3G_SMEM);
    k3g<<<144, 512, K3G_SMEM>>>(msg_fc2_b);

    cudaFuncSetAttribute(k5, cudaFuncAttributeMaxDynamicSharedMemorySize, K5_SMEM);
    k5<<<NNODE / 64, 256, K5_SMEM>>>((const float4*)inputs,
                                     out_fc1_w, out_fc1_b, out_fc2_w, out_fc2_b,
                                     out_fc3_w, out_fc3_b, out);
}

// round 12
// speedup vs baseline: 1.1399x; 1.1399x over previous
#include <cuda_runtime.h>
#include <cuda_fp16.h>
#include <cstdint>

#define NNODE 8192
#define NEDGE 253952

__device__ float  d_X  [NNODE * 64];
__device__ __half d_PQh[6 * NNODE * 256];      // [e*2+half][node][256] fp16
__device__ float  d_G  [3 * NEDGE];
__device__ float  d_AGGe[3 * NNODE * 256];     // per-expert partial agg
__device__ __half d_Wh[3 * 256 * 256];         // [e][n][k] fp16

__device__ __forceinline__ float lrelu(float v) { return fmaxf(v, 0.01f * v); }

__device__ __forceinline__ uint32_t smem_u32(const void* p) {
    uint32_t a;
    asm("{ .reg .u64 t; cvta.to.shared.u64 t, %1; cvt.u32.u64 %0, t; }" : "=r"(a) : "l"(p));
    return a;
}

#define CP_ASYNC16(dst, src) \
    asm volatile("cp.async.cg.shared.global [%0], [%1], 16;" :: "r"(dst), "l"(src) : "memory")
#define CP_COMMIT() asm volatile("cp.async.commit_group;" ::: "memory")
#define CP_WAIT(n)  asm volatile("cp.async.wait_group %0;" :: "n"(n) : "memory")

#define LDSM_X4(r, a) \
    asm volatile("ldmatrix.sync.aligned.m8n8.x4.shared.b16 {%0,%1,%2,%3}, [%4];" \
        : "=r"((r)[0]), "=r"((r)[1]), "=r"((r)[2]), "=r"((r)[3]) : "r"(a))
#define MMA16816(d, a, b) \
    asm volatile("mma.sync.aligned.m16n8k16.row.col.f32.f16.f16.f32 " \
        "{%0,%1,%2,%3}, {%4,%5,%6,%7}, {%8,%9}, {%0,%1,%2,%3};" \
        : "+f"((d)[0]), "+f"((d)[1]), "+f"((d)[2]), "+f"((d)[3]) \
        : "r"((a)[0]), "r"((a)[1]), "r"((a)[2]), "r"((a)[3]), "r"((b)[0]), "r"((b)[1]))

// ------------------------- k1x: node-layout transpose ----------------------
__global__ void k1x(const float4* __restrict__ in4) {
    int idx = blockIdx.x * blockDim.x + threadIdx.x;
    if (idx >= NNODE * 16) return;
    int n = idx >> 4, q = idx & 15;
    int b = n >> 11, t = (n >> 5) & 63, a = n & 31;
    ((float4*)d_X)[idx] = in4[(((b * 32 + a) * 64) + t) * 16 + q];
}

// ------------------------- k1g: edge gates ---------------------------------
__global__ void k1g(const float* __restrict__ state, const float4* __restrict__ rt4) {
    int idx = blockIdx.x * blockDim.x + threadIdx.x;
    if (idx >= NEDGE) return;
    int bt = idx / 992, r = idx - bt * 992;
    int b = bt >> 6, t = bt & 63;
    int rec = r / 31, j = r - rec * 31;
    int send = j + (j >= rec);
    const float4 st = *(const float4*)&state[(((b * 32 + send) * 64) + t) * 4];
    const float4* rt = rt4 + (b * 992 + r) * 4;
    float4 r0 = rt[0], r1 = rt[1], r2 = rt[2], r3 = rt[3];
    d_G[0 * NEDGE + idx] = st.x * r0.y + st.y * r1.y + st.z * r2.y + st.w * r3.y;
    d_G[1 * NEDGE + idx] = st.x * r0.z + st.y * r1.z + st.z * r2.z + st.w * r3.z;
    d_G[2 * NEDGE + idx] = st.x * r0.w + st.y * r1.w + st.z * r2.w + st.w * r3.w;
}

// ------------- k2: P/Q node GEMMs -> fp16 (64-row blocks, round-9) ---------
__global__ __launch_bounds__(256) void k2(const float* __restrict__ w1,
                                          const float* __restrict__ b1) {
    __shared__ float xs[64][64];
    int row0 = blockIdx.x * 64, tid = threadIdx.x;
    for (int i = tid; i < 64 * 64; i += 256) xs[i >> 6][i & 63] = d_X[row0 * 64 + i];
    __syncthreads();
    for (int chunk = 0; chunk < 6; ++chunk) {
        int e = chunk >> 1, half = chunk & 1;
        const float* W = w1 + ((size_t)((e + 1) * 128 + half * 64)) * 256;
        float acc[64];
#pragma unroll
        for (int m = 0; m < 64; ++m) acc[m] = 0.f;
#pragma unroll 2
        for (int k = 0; k < 64; ++k) {
            float w = W[k * 256 + tid];
#pragma unroll
            for (int m = 0; m < 64; ++m) acc[m] += xs[m][k] * w;
        }
        float bias = (half == 0) ? b1[(e + 1) * 256 + tid] : 0.f;
        __half* dst = d_PQh + ((size_t)chunk * NNODE + row0) * 256 + tid;
#pragma unroll
        for (int m = 0; m < 64; ++m) dst[m * 256] = __float2half(acc[m] + bias);
    }
}

// --------------- k2w: W2 transpose -> fp16 [e][n][k] -----------------------
__global__ void k2w(const float* __restrict__ w2) {
    __shared__ float tile[32][33];
    int e = blockIdx.z, kt = blockIdx.x * 32, nt = blockIdx.y * 32;
    int tx = threadIdx.x, ty = threadIdx.y;          // 32 x 8
#pragma unroll
    for (int r = 0; r < 4; ++r)
        tile[ty + r * 8][tx] = w2[((size_t)(e + 1) * 256 + kt + ty + r * 8) * 256 + nt + tx];
    __syncthreads();
#pragma unroll
    for (int r = 0; r < 4; ++r) {
        int n = nt + ty + r * 8;
        d_Wh[((size_t)e * 256 + n) * 256 + kt + tx] = __float2half(tile[tx][ty + r * 8]);
    }
}

// ------- k3h: B-resident fp16 HMMA, K-half A pipeline (overlapped) ---------
// Grid = 3 experts x 48 blocks; 43/42 quad-tiles. B (256x256) SMEM-resident.
// A in TWO fixed K-half buffers (128 rows x 256B, stride 272). Per tile:
//   mma(h0); sync; build(t+1,h0); mma(h1); sync; build(t+1,h1)+g; epi; sync
#define SB_B    0            // 256 x 528 = 135168
#define SB_A    135168       // 2 x (128 x 272) = 69632
#define SB_G    204800       // 2 x 512
#define SB_B2   205824       // 1024
#define K3H_SMEM 206848

__global__ __launch_bounds__(512, 1) void k3h(const float* __restrict__ b2) {
    extern __shared__ char smem[];
    uint32_t sb = smem_u32(smem);
    int tid = threadIdx.x, lane = tid & 31, wid = tid >> 5;
    int mwarp = wid >> 2, nwarp = wid & 3;
    int e = blockIdx.x / 48, jb = blockIdx.x % 48;
    int t0     = (jb < 32) ? jb * 43 : 32 * 43 + (jb - 32) * 42;
    int ntiles = (jb < 32) ? 43 : 42;

    float* g_s = (float*)(smem + SB_G);
    float* b2s = (float*)(smem + SB_B2);
    const __half* Pg = d_PQh + (size_t)(e * 2) * NNODE * 256;
    const __half* Qg = d_PQh + (size_t)(e * 2 + 1) * NNODE * 256;

    auto cvt = [](uint32_t pa, uint32_t qa) -> uint32_t {
        __half2 h = __hadd2(*(__half2*)&pa, *(__half2*)&qa);
        __half2 s = __hmul2(h, __float2half2_rn(0.01f));
        __half2 r = __hmax2(h, s);
        return *(uint32_t*)&r;
    };
    // build one K-half (128 k-elems) of A for tile t into fixed buffer h
    auto buildH = [&](int t, int h) {
        int m = tid >> 2, sub = tid & 3;
        int bt = t >> 3, a0 = (t & 7) * 4;
        int mq = m >> 5, jj = m & 31;
        int rec = a0 + mq;
        int send = (jj < 31) ? (jj + (jj >= rec)) : 0;   // dummy rows gated later
        const uint4* P4 = (const uint4*)(Pg + (size_t)(bt * 32 + send) * 256
                                         + h * 128 + sub * 32);
        const uint4* Q4 = (const uint4*)(Qg + (size_t)(bt * 32 + rec) * 256
                                         + h * 128 + sub * 32);
        uint4* dst = (uint4*)(smem + SB_A + h * 34816 + m * 272 + sub * 64);
#pragma unroll
        for (int q = 0; q < 4; ++q) {
            uint4 p = P4[q], qq = Q4[q];
            uint4 o;
            o.x = cvt(p.x, qq.x); o.y = cvt(p.y, qq.y);
            o.z = cvt(p.z, qq.z); o.w = cvt(p.w, qq.w);
            dst[q] = o;
        }
    };
    auto stageG = [&](int t) {
        if (tid < 128) {
            int bt = t >> 3, a0 = (t & 7) * 4;
            int grp = tid >> 5, jj = tid & 31;
            g_s[(t & 1) * 128 + tid] = (jj < 31)
                ? d_G[(size_t)e * NEDGE + bt * 992 + (a0 + grp) * 31 + jj] : 0.f;
        }
    };

    // ---- prologue: b2 + full B resident + first tile's A/g ----
    if (tid < 256) b2s[tid] = b2[(e + 1) * 256 + tid];
    {
        const __half* Wsrc = d_Wh + (size_t)e * 65536;
        for (int i = tid; i < 8192; i += 512) {
            int n = i >> 5, c = i & 31;
            CP_ASYNC16(sb + SB_B + (uint32_t)(n * 528 + c * 16),
                       (const char*)(Wsrc + n * 256 + c * 8));
        }
        CP_COMMIT();
    }
    buildH(t0, 0);
    buildH(t0, 1);
    stageG(t0);
    CP_WAIT(0);
    __syncthreads();

    uint32_t a_base = sb + SB_A
                    + (uint32_t)(mwarp * 32 + (lane & 7) + ((lane >> 3) & 1) * 8) * 272u
                    + ((lane >> 4) & 1) * 16u;
    uint32_t b_base = sb + SB_B
                    + (uint32_t)(nwarp * 64 + (lane & 7) + ((lane >> 4) & 1) * 8) * 528u
                    + ((lane >> 3) & 1) * 16u;

    for (int ti = 0; ti < ntiles; ++ti) {
        int t = t0 + ti;
        int bt = t >> 3, a0 = (t & 7) * 4;
        bool more = (ti + 1 < ntiles);

        float acc[2][8][4];
#pragma unroll
        for (int ms = 0; ms < 2; ++ms)
#pragma unroll
            for (int ns = 0; ns < 8; ++ns)
#pragma unroll
                for (int c = 0; c < 4; ++c) acc[ms][ns][c] = 0.f;

#pragma unroll
        for (int h = 0; h < 2; ++h) {
            uint32_t a_l = a_base + (uint32_t)h * 34816u;
            uint32_t b_h = b_base + (uint32_t)h * 256u;
#pragma unroll
            for (int ks = 0; ks < 8; ++ks) {
                uint32_t koff = (uint32_t)(ks * 32);
                uint32_t af0[4], af1[4];
                LDSM_X4(af0, a_l + koff);
                LDSM_X4(af1, a_l + 16 * 272 + koff);
                uint32_t bfA[4], bfB[4];
                LDSM_X4(bfA, b_h + koff);                       // p = 0
#pragma unroll
                for (int p = 0; p < 4; ++p) {
                    uint32_t* cur = (p & 1) ? bfB : bfA;
                    uint32_t* nxt = (p & 1) ? bfA : bfB;
                    if (p < 3) LDSM_X4(nxt, b_h + (p + 1) * 8448 + koff);
                    MMA16816(acc[0][2 * p],     af0, cur);
                    MMA16816(acc[0][2 * p + 1], af0, cur + 2);
                    MMA16816(acc[1][2 * p],     af1, cur);
                    MMA16816(acc[1][2 * p + 1], af1, cur + 2);
                }
            }
            __syncthreads();                 // half-h LDSM reads complete
            if (more) {
                buildH(t + 1, h);            // overlaps tensor-pipe drain
                if (h == 1) stageG(t + 1);
            }
        }

        // ---- epilogue: bias + lrelu + gate, reduce 32 rows/warp ----
        {
            const float* gs = g_s + (t & 1) * 128;
            float g00 = gs[mwarp * 32 + (lane >> 2)];
            float g01 = gs[mwarp * 32 + (lane >> 2) + 8];
            float g10 = gs[mwarp * 32 + 16 + (lane >> 2)];
            float g11 = gs[mwarp * 32 + 24 + (lane >> 2)];
            int node = bt * 32 + a0 + mwarp;
#pragma unroll
            for (int nst = 0; nst < 8; ++nst) {
                int c0 = nwarp * 64 + nst * 8 + (lane & 3) * 2;
                float b0v = b2s[c0], b1v = b2s[c0 + 1];
                float s0 = lrelu(acc[0][nst][0] + b0v) * g00 + lrelu(acc[0][nst][2] + b0v) * g01
                         + lrelu(acc[1][nst][0] + b0v) * g10 + lrelu(acc[1][nst][2] + b0v) * g11;
                float s1 = lrelu(acc[0][nst][1] + b1v) * g00 + lrelu(acc[0][nst][3] + b1v) * g01
                         + lrelu(acc[1][nst][1] + b1v) * g10 + lrelu(acc[1][nst][3] + b1v) * g11;
                s0 += __shfl_xor_sync(~0u, s0, 4);  s1 += __shfl_xor_sync(~0u, s1, 4);
                s0 += __shfl_xor_sync(~0u, s0, 8);  s1 += __shfl_xor_sync(~0u, s1, 8);
                s0 += __shfl_xor_sync(~0u, s0, 16); s1 += __shfl_xor_sync(~0u, s1, 16);
                if (lane < 4) {
                    float* dst = d_AGGe + ((size_t)e * NNODE + node) * 256 + c0;
                    dst[0] = s0; dst[1] = s1;
                }
            }
        }
        __syncthreads();                     // builds + g done before next tile
    }
}

// --------- k5: output MLP + residual (64-row blocks, round-9) --------------
#define K5_SMEM (64 * 320 * 4 + 64 * 256 * 4)   // aug + hbuf = 147456

__global__ __launch_bounds__(256) void k5(const float* __restrict__ fw1,
                                          const float* __restrict__ fb1,
                                          const float* __restrict__ fw2,
                                          const float* __restrict__ fb2,
                                          const float* __restrict__ fw3,
                                          const float* __restrict__ fb3,
                                          float* __restrict__ out) {
    extern __shared__ float sm5[];
    float* aug  = sm5;               // [64][320]
    float* hbuf = sm5 + 64 * 320;    // [64][256]
    int row0 = blockIdx.x * 64, tid = threadIdx.x;

    for (int i = tid; i < 64 * 64; i += 256)
        aug[(i >> 6) * 320 + (i & 63)] = d_X[row0 * 64 + i];
    for (int i = tid; i < 64 * 256; i += 256) {
        size_t base = (size_t)row0 * 256 + i;
        aug[(i >> 8) * 320 + 64 + (i & 255)] = d_AGGe[base]
                                             + d_AGGe[(size_t)NNODE * 256 + base]
                                             + d_AGGe[(size_t)2 * NNODE * 256 + base];
    }
    __syncthreads();

    {
        float acc[64];
#pragma unroll
        for (int m = 0; m < 64; ++m) acc[m] = 0.f;
#pragma unroll 2
        for (int k = 0; k < 320; ++k) {
            float w = fw1[k * 256 + tid];
#pragma unroll
            for (int m = 0; m < 64; ++m) acc[m] += aug[m * 320 + k] * w;
        }
        float b = fb1[tid];
#pragma unroll
        for (int m = 0; m < 64; ++m) hbuf[m * 256 + tid] = lrelu(acc[m] + b);
    }
    __syncthreads();

    {
        float acc[64];
#pragma unroll
        for (int m = 0; m < 64; ++m) acc[m] = 0.f;
#pragma unroll 2
        for (int k = 0; k < 256; ++k) {
            float w = fw2[k * 256 + tid];
#pragma unroll
            for (int m = 0; m < 64; ++m) acc[m] += hbuf[m * 256 + k] * w;
        }
        float b = fb2[tid];
#pragma unroll
        for (int m = 0; m < 64; ++m) aug[m * 320 + tid] = lrelu(acc[m] + b);
    }
    __syncthreads();

    {
        int c = tid & 63, sub = tid >> 6;       // 4 subs x 16 rows
        float acc3[16];
#pragma unroll
        for (int mm = 0; mm < 16; ++mm) acc3[mm] = 0.f;
#pragma unroll 2
        for (int k = 0; k < 256; ++k) {
            float w = fw3[k * 64 + c];
#pragma unroll
            for (int mm = 0; mm < 16; ++mm)
                acc3[mm] += aug[(sub * 16 + mm) * 320 + k] * w;
        }
        float b = fb3[c];
#pragma unroll
        for (int mm = 0; mm < 16; ++mm) {
            int n = row0 + sub * 16 + mm;
            int bb = n >> 11, t = (n >> 5) & 63, a = n & 31;
            if (t < 63)
                out[(((bb * 32 + a) * 63) + t) * 64 + c] = d_X[n * 64 + c] + acc3[mm] + b;
        }
    }
}

// ---------------------------------------------------------------------------
extern "C" void kernel_launch(void* const* d_in, const int* in_sizes, int n_in,
                              void* d_out, int out_size) {
    (void)in_sizes; (void)n_in; (void)out_size;
    const float* inputs    = (const float*)d_in[0];
    const float* state     = (const float*)d_in[1];
    const float* rel_type  = (const float*)d_in[2];
    const float* msg_fc1_w = (const float*)d_in[5];
    const float* msg_fc1_b = (const float*)d_in[6];
    const float* msg_fc2_w = (const float*)d_in[7];
    const float* msg_fc2_b = (const float*)d_in[8];
    const float* out_fc1_w = (const float*)d_in[9];
    const float* out_fc1_b = (const float*)d_in[10];
    const float* out_fc2_w = (const float*)d_in[11];
    const float* out_fc2_b = (const float*)d_in[12];
    const float* out_fc3_w = (const float*)d_in[13];
    const float* out_fc3_b = (const float*)d_in[14];
    float* out = (float*)d_out;

    k1x<<<(NNODE * 16 + 255) / 256, 256>>>((const float4*)inputs);
    k1g<<<(NEDGE + 255) / 256, 256>>>(state, (const float4*)rel_type);
    k2<<<NNODE / 64, 256>>>(msg_fc1_w, msg_fc1_b);
    k2w<<<dim3(8, 8, 3), dim3(32, 8)>>>(msg_fc2_w);

    cudaFuncSetAttribute(k3h, cudaFuncAttributeMaxDynamicSharedMemorySize, K3H_SMEM);
    k3h<<<144, 512, K3H_SMEM>>>(msg_fc2_b);

    cudaFuncSetAttribute(k5, cudaFuncAttributeMaxDynamicSharedMemorySize, K5_SMEM);
    k5<<<NNODE / 64, 256, K5_SMEM>>>(out_fc1_w, out_fc1_b, out_fc2_w, out_fc2_b,
                                     out_fc3_w, out_fc3_b, out);
}